// round 8
// baseline (speedup 1.0000x reference)
#include <cuda_runtime.h>
#include <math.h>
#include <float.h>

typedef unsigned long long u64;

#define B_ 8
#define T_ 4096
#define D_ 768
#define S_ 64
#define F_ 3072

// -------- scratch (device globals; no allocation allowed) --------
__device__ float g_xn[B_*T_*D_];
__device__ float g_tinv[B_*T_];
__device__ float g_sl[S_*D_];
__device__ float g_logits[B_*S_*T_];
__device__ float g_disp[B_*S_*T_];
__device__ float g_comb[B_*S_*T_];
__device__ float g_y[B_*S_*D_];
__device__ float g_h[B_*S_*F_];
__device__ float g_y2[B_*S_*D_];

// -------- packed f32x2 helpers --------
__device__ __forceinline__ u64 ffma2(u64 a, u64 b, u64 c){
    u64 d; asm("fma.rn.f32x2 %0, %1, %2, %3;" : "=l"(d) : "l"(a), "l"(b), "l"(c)); return d;
}
__device__ __forceinline__ u64 pack2(float lo, float hi){
    u64 r; asm("mov.b64 %0, {%1, %2};" : "=l"(r) : "f"(lo), "f"(hi)); return r;
}
__device__ __forceinline__ float2 unpack2(u64 v){
    float2 r; asm("mov.b64 {%0, %1}, %2;" : "=f"(r.x), "=f"(r.y) : "l"(v)); return r;
}
__device__ __forceinline__ float gelu_f(float x){
    return 0.5f * x * (1.0f + erff(x * 0.7071067811865476f));
}

__device__ __forceinline__ float blk_sum(float v, volatile float* sbuf){
    #pragma unroll
    for (int o = 16; o; o >>= 1) v += __shfl_xor_sync(0xffffffffu, v, o);
    __syncthreads();
    if ((threadIdx.x & 31) == 0) sbuf[threadIdx.x >> 5] = v;
    __syncthreads();
    if (threadIdx.x < 32){
        int nw = blockDim.x >> 5;
        float r = (threadIdx.x < (unsigned)nw) ? sbuf[threadIdx.x] : 0.0f;
        #pragma unroll
        for (int o = 16; o; o >>= 1) r += __shfl_xor_sync(0xffffffffu, r, o);
        if (threadIdx.x == 0) sbuf[0] = r;
    }
    __syncthreads();
    return sbuf[0];
}
__device__ __forceinline__ float blk_max(float v, volatile float* sbuf){
    #pragma unroll
    for (int o = 16; o; o >>= 1) v = fmaxf(v, __shfl_xor_sync(0xffffffffu, v, o));
    __syncthreads();
    if ((threadIdx.x & 31) == 0) sbuf[threadIdx.x >> 5] = v;
    __syncthreads();
    if (threadIdx.x < 32){
        int nw = blockDim.x >> 5;
        float r = (threadIdx.x < (unsigned)nw) ? sbuf[threadIdx.x] : -FLT_MAX;
        #pragma unroll
        for (int o = 16; o; o >>= 1) r = fmaxf(r, __shfl_xor_sync(0xffffffffu, r, o));
        if (threadIdx.x == 0) sbuf[0] = r;
    }
    __syncthreads();
    return sbuf[0];
}

// K0: zero accumulators (B*S*D = 393216 floats = 98304 float4 each)
__global__ void k_zero(){
    int i = blockIdx.x * blockDim.x + threadIdx.x;
    float4 z = make_float4(0.f,0.f,0.f,0.f);
    ((float4*)g_y)[i]  = z;
    ((float4*)g_y2)[i] = z;
}

// K1: sl = l2_normalize(slots) * scale
__global__ __launch_bounds__(256) void k_slot_prep(const float* __restrict__ slots,
                                                   const float* __restrict__ scale){
    __shared__ float sbuf[32];
    int s = blockIdx.x;
    float acc = 0.f;
    for (int d = threadIdx.x; d < D_; d += 256){ float v = slots[s*D_+d]; acc += v*v; }
    float tot = blk_sum(acc, sbuf);
    float m = scale[s] / fmaxf(sqrtf(tot), 1e-5f);
    for (int d = threadIdx.x; d < D_; d += 256) g_sl[s*D_+d] = slots[s*D_+d] * m;
}

// K2: RMSNorm + token inverse l2 norm
__global__ __launch_bounds__(256) void k_rms(const float* __restrict__ x,
                                             const float* __restrict__ w){
    __shared__ float sbuf[32];
    int row = blockIdx.x;
    const float* xr = x + (size_t)row * D_;
    float s1 = 0.f, s2 = 0.f;
    float vw[3];
    #pragma unroll
    for (int i = 0; i < 3; i++){
        int d = threadIdx.x + i*256;
        float v = xr[d];
        float t = v * w[d];
        vw[i] = t;
        s1 += v*v; s2 += t*t;
    }
    float t1 = blk_sum(s1, sbuf);
    float t2 = blk_sum(s2, sbuf);
    float rs = rsqrtf(t1 * (1.0f / D_) + 1e-5f);
    float nrm = rs * sqrtf(t2);
    if (threadIdx.x == 0) g_tinv[row] = 1.0f / fmaxf(nrm, 1e-5f);
    float* xo = g_xn + (size_t)row * D_;
    #pragma unroll
    for (int i = 0; i < 3; i++) xo[threadIdx.x + i*256] = vw[i] * rs;
}

// K3: logits[b][s][t] = (sl[s] . xn[b][t]) * tinv[b][t]
__global__ __launch_bounds__(256) void k_logits(){
    int b = blockIdx.y;
    int t0 = blockIdx.x * 64;
    __shared__ __align__(16) float As[16][68];
    __shared__ __align__(16) float Bs[16][68];
    int tid = threadIdx.x;
    int tx = tid & 15, ty = tid >> 4;
    u64 acc[2][4];
    #pragma unroll
    for (int i = 0; i < 2; i++)
        #pragma unroll
        for (int j = 0; j < 4; j++) acc[i][j] = 0ull;

    int rA = tid >> 2;
    int kq = (tid & 3) << 2;
    const float* aB = g_sl + rA * D_ + kq;
    const float* bB = g_xn + (size_t)(b * T_ + t0 + rA) * D_ + kq;

    for (int kb = 0; kb < D_; kb += 16){
        float4 av = *(const float4*)(aB + kb);
        float4 bv = *(const float4*)(bB + kb);
        As[kq+0][rA]=av.x; As[kq+1][rA]=av.y; As[kq+2][rA]=av.z; As[kq+3][rA]=av.w;
        Bs[kq+0][rA]=bv.x; Bs[kq+1][rA]=bv.y; Bs[kq+2][rA]=bv.z; Bs[kq+3][rA]=bv.w;
        __syncthreads();
        #pragma unroll
        for (int k = 0; k < 16; k++){
            ulonglong2 a2 = *(const ulonglong2*)&As[k][ty << 2];
            float4 b4 = *(const float4*)&Bs[k][tx << 2];
            u64 b0=pack2(b4.x,b4.x), b1=pack2(b4.y,b4.y), b2=pack2(b4.z,b4.z), b3=pack2(b4.w,b4.w);
            acc[0][0]=ffma2(a2.x,b0,acc[0][0]); acc[1][0]=ffma2(a2.y,b0,acc[1][0]);
            acc[0][1]=ffma2(a2.x,b1,acc[0][1]); acc[1][1]=ffma2(a2.y,b1,acc[1][1]);
            acc[0][2]=ffma2(a2.x,b2,acc[0][2]); acc[1][2]=ffma2(a2.y,b2,acc[1][2]);
            acc[0][3]=ffma2(a2.x,b3,acc[0][3]); acc[1][3]=ffma2(a2.y,b3,acc[1][3]);
        }
        __syncthreads();
    }
    int tbase = t0 + (tx << 2);
    float tv[4];
    #pragma unroll
    for (int j = 0; j < 4; j++) tv[j] = g_tinv[b * T_ + tbase + j];
    int s0 = ty << 2;
    #pragma unroll
    for (int i2 = 0; i2 < 2; i2++)
        #pragma unroll
        for (int j = 0; j < 4; j++){
            float2 p = unpack2(acc[i2][j]);
            g_logits[(size_t)(b*S_ + s0 + i2*2 + 0) * T_ + tbase + j] = p.x * tv[j];
            g_logits[(size_t)(b*S_ + s0 + i2*2 + 1) * T_ + tbase + j] = p.y * tv[j];
        }
}

// K4: dispatch softmax over T per (b,s)
__global__ __launch_bounds__(256) void k_disp_soft(){
    __shared__ float sm[T_];
    __shared__ float sbuf[32];
    int s = blockIdx.x, b = blockIdx.y;
    const float* row = g_logits + (size_t)(b*S_ + s) * T_;
    float mx = -FLT_MAX;
    for (int i = threadIdx.x; i < T_; i += 256) mx = fmaxf(mx, row[i]);
    mx = blk_max(mx, sbuf);
    float sum = 0.f;
    for (int i = threadIdx.x; i < T_; i += 256){
        float e = expf(row[i] - mx); sm[i] = e; sum += e;
    }
    sum = blk_sum(sum, sbuf);
    float inv = 1.0f / sum;
    float* o = g_disp + (size_t)(b*S_ + s) * T_;
    for (int i = threadIdx.x; i < T_; i += 256) o[i] = sm[i] * inv;
}

// K5: combine softmax over S per (b,t)
__global__ __launch_bounds__(128) void k_comb_soft(){
    int b = blockIdx.y;
    int t = blockIdx.x * 128 + threadIdx.x;
    float v[S_];
    float mx = -FLT_MAX;
    #pragma unroll
    for (int s = 0; s < S_; s++){ v[s] = g_logits[(size_t)(b*S_+s)*T_ + t]; mx = fmaxf(mx, v[s]); }
    float sum = 0.f;
    #pragma unroll
    for (int s = 0; s < S_; s++){ v[s] = expf(v[s] - mx); sum += v[s]; }
    float inv = 1.0f / sum;
    #pragma unroll
    for (int s = 0; s < S_; s++) g_comb[(size_t)(b*S_+s)*T_ + t] = v[s] * inv;
}

// K6: y[b][s][d] = sum_t disp[b][s][t] * xn[b][t][d]   (split-K=4, atomicAdd)
__global__ __launch_bounds__(256) void k_dispatch(){
    int b = blockIdx.y;
    int d0 = blockIdx.x * 64;
    int kz = blockIdx.z;
    __shared__ __align__(16) float As[16][68];
    __shared__ __align__(16) float Bs[16][68];
    int tid = threadIdx.x;
    int tx = tid & 15, ty = tid >> 4;
    u64 acc[2][4];
    #pragma unroll
    for (int i = 0; i < 2; i++)
        #pragma unroll
        for (int j = 0; j < 4; j++) acc[i][j] = 0ull;

    int sA = tid >> 2, kqA = (tid & 3) << 2;
    int kB = tid >> 4, dq = (tid & 15) << 2;
    const float* aB = g_disp + (size_t)(b*S_ + sA) * T_ + kz*1024 + kqA;
    const float* bB = g_xn + (size_t)(b*T_ + kz*1024 + kB) * D_ + d0 + dq;

    for (int kb = 0; kb < 1024; kb += 16){
        float4 av = *(const float4*)(aB + kb);
        float4 bv = *(const float4*)(bB + (size_t)kb * D_);
        As[kqA+0][sA]=av.x; As[kqA+1][sA]=av.y; As[kqA+2][sA]=av.z; As[kqA+3][sA]=av.w;
        *(float4*)&Bs[kB][dq] = bv;
        __syncthreads();
        #pragma unroll
        for (int k = 0; k < 16; k++){
            ulonglong2 a2 = *(const ulonglong2*)&As[k][ty << 2];
            float4 b4 = *(const float4*)&Bs[k][tx << 2];
            u64 b0=pack2(b4.x,b4.x), b1=pack2(b4.y,b4.y), b2=pack2(b4.z,b4.z), b3=pack2(b4.w,b4.w);
            acc[0][0]=ffma2(a2.x,b0,acc[0][0]); acc[1][0]=ffma2(a2.y,b0,acc[1][0]);
            acc[0][1]=ffma2(a2.x,b1,acc[0][1]); acc[1][1]=ffma2(a2.y,b1,acc[1][1]);
            acc[0][2]=ffma2(a2.x,b2,acc[0][2]); acc[1][2]=ffma2(a2.y,b2,acc[1][2]);
            acc[0][3]=ffma2(a2.x,b3,acc[0][3]); acc[1][3]=ffma2(a2.y,b3,acc[1][3]);
        }
        __syncthreads();
    }
    int dbase = d0 + (tx << 2);
    int s0 = ty << 2;
    #pragma unroll
    for (int i2 = 0; i2 < 2; i2++)
        #pragma unroll
        for (int j = 0; j < 4; j++){
            float2 p = unpack2(acc[i2][j]);
            atomicAdd(&g_y[(size_t)(b*S_ + s0 + i2*2 + 0) * D_ + dbase + j], p.x);
            atomicAdd(&g_y[(size_t)(b*S_ + s0 + i2*2 + 1) * D_ + dbase + j], p.y);
        }
}

// K7: h[b][s][f] = gelu(sum_d y[b][s][d]*W1[s][d][f] + b1[s][f])
__global__ __launch_bounds__(128) void k_ffn1(const float* __restrict__ W1,
                                              const float* __restrict__ b1){
    int s = blockIdx.y;
    int f0 = blockIdx.x * 512 + threadIdx.x * 4;
    __shared__ u64 ys2[8][D_];
    for (int i = threadIdx.x; i < 8*D_; i += 128){
        int bb = i / D_, d = i - bb*D_;
        float v = g_y[(size_t)(bb*S_ + s) * D_ + d];
        ys2[bb][d] = pack2(v, v);
    }
    __syncthreads();

    u64 acc[8][2];
    #pragma unroll
    for (int bb = 0; bb < 8; bb++){ acc[bb][0]=0ull; acc[bb][1]=0ull; }

    const char* wp = (const char*)(W1 + (size_t)s * D_ * F_ + f0);
    for (int d0 = 0; d0 < D_; d0 += 8){
        ulonglong2 w[8];
        #pragma unroll
        for (int u = 0; u < 8; u++)
            w[u] = *(const ulonglong2*)(wp + (size_t)(d0 + u) * (F_ * 4));
        #pragma unroll
        for (int u = 0; u < 8; u++)
            #pragma unroll
            for (int bb = 0; bb < 8; bb++){
                u64 yv = ys2[bb][d0 + u];
                acc[bb][0] = ffma2(w[u].x, yv, acc[bb][0]);
                acc[bb][1] = ffma2(w[u].y, yv, acc[bb][1]);
            }
    }
    float4 bias = *(const float4*)&b1[s * F_ + f0];
    #pragma unroll
    for (int bb = 0; bb < 8; bb++){
        float2 p0 = unpack2(acc[bb][0]);
        float2 p1 = unpack2(acc[bb][1]);
        float4 o;
        o.x = gelu_f(p0.x + bias.x);
        o.y = gelu_f(p0.y + bias.y);
        o.z = gelu_f(p1.x + bias.z);
        o.w = gelu_f(p1.y + bias.w);
        *(float4*)&g_h[(size_t)(bb*S_ + s) * F_ + f0] = o;
    }
}

// K8: y2[b][s][d] += sum_f h[b][s][f]*W2[s][f][d]   (split-K=4)
__global__ __launch_bounds__(96) void k_ffn2(const float* __restrict__ W2){
    int s = blockIdx.y;
    int kz = blockIdx.z;
    int d0 = blockIdx.x * 384 + threadIdx.x * 4;
    __shared__ u64 hs2[8][768];
    for (int i = threadIdx.x; i < 8*768; i += 96){
        int bb = i / 768, ff = i - bb*768;
        float v = g_h[(size_t)(bb*S_ + s) * F_ + kz*768 + ff];
        hs2[bb][ff] = pack2(v, v);
    }
    __syncthreads();

    u64 acc[8][2];
    #pragma unroll
    for (int bb = 0; bb < 8; bb++){ acc[bb][0]=0ull; acc[bb][1]=0ull; }

    const char* wp = (const char*)(W2 + ((size_t)s * F_ + kz*768) * D_ + d0);
    for (int f0 = 0; f0 < 768; f0 += 8){
        ulonglong2 w[8];
        #pragma unroll
        for (int u = 0; u < 8; u++)
            w[u] = *(const ulonglong2*)(wp + (size_t)(f0 + u) * (D_ * 4));
        #pragma unroll
        for (int u = 0; u < 8; u++)
            #pragma unroll
            for (int bb = 0; bb < 8; bb++){
                u64 hv = hs2[bb][f0 + u];
                acc[bb][0] = ffma2(w[u].x, hv, acc[bb][0]);
                acc[bb][1] = ffma2(w[u].y, hv, acc[bb][1]);
            }
    }
    #pragma unroll
    for (int bb = 0; bb < 8; bb++){
        float2 p0 = unpack2(acc[bb][0]);
        float2 p1 = unpack2(acc[bb][1]);
        float* dst = &g_y2[(size_t)(bb*S_ + s) * D_ + d0];
        atomicAdd(dst + 0, p0.x);
        atomicAdd(dst + 1, p0.y);
        atomicAdd(dst + 2, p1.x);
        atomicAdd(dst + 3, p1.y);
    }
}

// K9: out[b][t][d] = sum_s (y2[b][s][d]+b2[s][d]) * comb[b][s][t]
__global__ __launch_bounds__(256) void k_final(const float* __restrict__ b2,
                                               float* __restrict__ out){
    int b = blockIdx.z;
    int d1 = blockIdx.y;
    int t0 = blockIdx.x * 64;
    __shared__ __align__(16) float Ys[S_][128];
    __shared__ __align__(16) float Ws[S_][64];
    int tid = threadIdx.x;

    for (int i = tid; i < 2048; i += 256){
        int s = i >> 5;
        int dq = (i & 31) << 2;
        int gd = d1*128 + dq;
        float4 yv = *(const float4*)&g_y2[(size_t)(b*S_ + s) * D_ + gd];
        float4 bv = *(const float4*)&b2[s * D_ + gd];
        yv.x += bv.x; yv.y += bv.y; yv.z += bv.z; yv.w += bv.w;
        *(float4*)&Ys[s][dq] = yv;
    }
    for (int i = tid; i < 1024; i += 256){
        int s = i >> 4;
        int tq = (i & 15) << 2;
        *(float4*)&Ws[s][tq] = *(const float4*)&g_comb[(size_t)(b*S_ + s) * T_ + t0 + tq];
    }
    __syncthreads();

    int tx = tid & 15;    // 16 groups of 8 d
    int ty = tid >> 4;    // 16 groups of 4 t
    u64 acc[4][4];
    #pragma unroll
    for (int j = 0; j < 4; j++)
        #pragma unroll
        for (int p = 0; p < 4; p++) acc[j][p] = 0ull;

    #pragma unroll 4
    for (int s = 0; s < S_; s++){
        float4 wv = *(const float4*)&Ws[s][ty << 2];
        ulonglong2 ya = *(const ulonglong2*)&Ys[s][tx << 3];
        ulonglong2 yb = *(const ulonglong2*)&Ys[s][(tx << 3) + 4];
        u64 w0=pack2(wv.x,wv.x), w1=pack2(wv.y,wv.y), w2s=pack2(wv.z,wv.z), w3=pack2(wv.w,wv.w);
        acc[0][0]=ffma2(ya.x,w0,acc[0][0]); acc[0][1]=ffma2(ya.y,w0,acc[0][1]);
        acc[0][2]=ffma2(yb.x,w0,acc[0][2]); acc[0][3]=ffma2(yb.y,w0,acc[0][3]);
        acc[1][0]=ffma2(ya.x,w1,acc[1][0]); acc[1][1]=ffma2(ya.y,w1,acc[1][1]);
        acc[1][2]=ffma2(yb.x,w1,acc[1][2]); acc[1][3]=ffma2(yb.y,w1,acc[1][3]);
        acc[2][0]=ffma2(ya.x,w2s,acc[2][0]); acc[2][1]=ffma2(ya.y,w2s,acc[2][1]);
        acc[2][2]=ffma2(yb.x,w2s,acc[2][2]); acc[2][3]=ffma2(yb.y,w2s,acc[2][3]);
        acc[3][0]=ffma2(ya.x,w3,acc[3][0]); acc[3][1]=ffma2(ya.y,w3,acc[3][1]);
        acc[3][2]=ffma2(yb.x,w3,acc[3][2]); acc[3][3]=ffma2(yb.y,w3,acc[3][3]);
    }

    #pragma unroll
    for (int j = 0; j < 4; j++){
        float2 p0 = unpack2(acc[j][0]);
        float2 p1 = unpack2(acc[j][1]);
        float2 p2 = unpack2(acc[j][2]);
        float2 p3 = unpack2(acc[j][3]);
        int t = t0 + (ty << 2) + j;
        float* dst = out + (size_t)(b * T_ + t) * D_ + d1*128 + (tx << 3);
        *(float4*)dst       = make_float4(p0.x, p0.y, p1.x, p1.y);
        *(float4*)(dst + 4) = make_float4(p2.x, p2.y, p3.x, p3.y);
    }
}

// -------- launch --------
extern "C" void kernel_launch(void* const* d_in, const int* in_sizes, int n_in,
                              void* d_out, int out_size){
    const float* x     = (const float*)d_in[0];
    const float* slots = (const float*)d_in[1];
    const float* scale = (const float*)d_in[2];
    const float* fc1_w = (const float*)d_in[3];
    const float* fc1_b = (const float*)d_in[4];
    const float* fc2_w = (const float*)d_in[5];
    const float* fc2_b = (const float*)d_in[6];
    const float* nw    = (const float*)d_in[7];
    float* out = (float*)d_out;

    k_zero<<<384, 256>>>();
    k_slot_prep<<<S_, 256>>>(slots, scale);
    k_rms<<<B_*T_, 256>>>(x, nw);
    k_logits<<<dim3(T_/64, B_), 256>>>();
    k_disp_soft<<<dim3(S_, B_), 256>>>();
    k_comb_soft<<<dim3(T_/128, B_), 128>>>();
    k_dispatch<<<dim3(D_/64, B_, 4), 256>>>();
    k_ffn1<<<dim3(F_/512, S_), 128>>>(fc1_w, fc1_b);
    k_ffn2<<<dim3(2, S_, 4), 96>>>(fc2_w);
    k_final<<<dim3(T_/64, D_/128, B_), 256>>>(fc2_b, out);
}